// round 1
// baseline (speedup 1.0000x reference)
#include <cuda_runtime.h>
#include <math.h>

#define N_TOK 4096
#define D_DIM 512

// ---------------- scratch (device globals; no cudaMalloc allowed) ----------
static __device__ float g_Q [N_TOK * D_DIM];
static __device__ float g_K [N_TOK * D_DIM];
static __device__ float g_V [N_TOK * D_DIM];
static __device__ float g_S [(size_t)N_TOK * N_TOK];
static __device__ float g_X1[N_TOK * D_DIM];
static __device__ float g_X2[N_TOK * D_DIM];
static __device__ float g_H [N_TOK * D_DIM];

// ---------------- GEMM NN: C[N,M] = A[N,K] @ B[K,M] (+biasVec)(+relu)(+resid)
// 64x64 block tile, BK=16, 256 threads, 4x4 per thread.
__global__ __launch_bounds__(256) void gemm_nn_kernel(
    const float* __restrict__ A, const float* __restrict__ B, float* __restrict__ C,
    int Kdim, int Mcols,
    const float* __restrict__ biasVec, const float* __restrict__ resid, int relu)
{
    __shared__ float As[16][64];
    __shared__ float Bs[16][64];
    const int tid = threadIdx.x;
    const int tx = tid & 15, ty = tid >> 4;
    const int bm = blockIdx.y * 64, bn = blockIdx.x * 64;

    const int a_r = tid >> 2;          // 0..63 row in tile
    const int a_k = (tid & 3) << 2;    // 0,4,8,12
    const int b_k = tid >> 4;          // 0..15
    const int b_n = (tid & 15) << 2;   // 0..60

    const float* Aptr = A + (size_t)(bm + a_r) * Kdim + a_k;
    const float* Bptr = B + (size_t)b_k * Mcols + bn + b_n;

    float acc[4][4] = {};
    for (int k0 = 0; k0 < Kdim; k0 += 16) {
        float4 av = *(const float4*)(Aptr + k0);
        As[a_k + 0][a_r] = av.x;
        As[a_k + 1][a_r] = av.y;
        As[a_k + 2][a_r] = av.z;
        As[a_k + 3][a_r] = av.w;
        *(float4*)&Bs[b_k][b_n] = *(const float4*)(Bptr + (size_t)k0 * Mcols);
        __syncthreads();
#pragma unroll
        for (int k = 0; k < 16; k++) {
            float4 a4 = *(const float4*)&As[k][ty << 2];
            float4 b4 = *(const float4*)&Bs[k][tx << 2];
            float ar[4] = {a4.x, a4.y, a4.z, a4.w};
            float br[4] = {b4.x, b4.y, b4.z, b4.w};
#pragma unroll
            for (int i = 0; i < 4; i++)
#pragma unroll
                for (int j = 0; j < 4; j++)
                    acc[i][j] += ar[i] * br[j];
        }
        __syncthreads();
    }

#pragma unroll
    for (int i = 0; i < 4; i++) {
        const int r = bm + (ty << 2) + i;
#pragma unroll
        for (int j = 0; j < 4; j++) {
            const int c = bn + (tx << 2) + j;
            float v = acc[i][j];
            if (biasVec) v += biasVec[c];
            if (relu)    v = fmaxf(v, 0.0f);
            if (resid)   v += resid[(size_t)r * Mcols + c];
            C[(size_t)r * Mcols + c] = v;
        }
    }
}

// ---------------- GEMM NT: C[N,4096] = A[N,K] @ B[4096,K]^T * scale + bias
// bias: gauss ? exp(-b^2/200) : b   (fused attention-bias epilogue)
__global__ __launch_bounds__(256) void gemm_nt_kernel(
    const float* __restrict__ A, const float* __restrict__ B, float* __restrict__ C,
    int Kdim, float scale, const float* __restrict__ biasMat, int gauss)
{
    __shared__ float As[16][64];
    __shared__ float Bs[16][64];
    const int tid = threadIdx.x;
    const int tx = tid & 15, ty = tid >> 4;
    const int bm = blockIdx.y * 64, bn = blockIdx.x * 64;

    const int r4 = tid >> 2;
    const int k4 = (tid & 3) << 2;

    const float* Aptr = A + (size_t)(bm + r4) * Kdim + k4;
    const float* Bptr = B + (size_t)(bn + r4) * Kdim + k4;

    float acc[4][4] = {};
    for (int k0 = 0; k0 < Kdim; k0 += 16) {
        float4 av = *(const float4*)(Aptr + k0);
        float4 bv = *(const float4*)(Bptr + k0);
        As[k4 + 0][r4] = av.x; As[k4 + 1][r4] = av.y;
        As[k4 + 2][r4] = av.z; As[k4 + 3][r4] = av.w;
        Bs[k4 + 0][r4] = bv.x; Bs[k4 + 1][r4] = bv.y;
        Bs[k4 + 2][r4] = bv.z; Bs[k4 + 3][r4] = bv.w;
        __syncthreads();
#pragma unroll
        for (int k = 0; k < 16; k++) {
            float4 a4 = *(const float4*)&As[k][ty << 2];
            float4 b4 = *(const float4*)&Bs[k][tx << 2];
            float ar[4] = {a4.x, a4.y, a4.z, a4.w};
            float br[4] = {b4.x, b4.y, b4.z, b4.w};
#pragma unroll
            for (int i = 0; i < 4; i++)
#pragma unroll
                for (int j = 0; j < 4; j++)
                    acc[i][j] += ar[i] * br[j];
        }
        __syncthreads();
    }

    const float inv2s2 = 0.005f;  // 1/(2*SIGMA^2), SIGMA=10
#pragma unroll
    for (int i = 0; i < 4; i++) {
        const int r = bm + (ty << 2) + i;
#pragma unroll
        for (int j = 0; j < 4; j++) {
            const int c = bn + (tx << 2) + j;
            float bias = biasMat[(size_t)r * N_TOK + c];
            if (gauss) bias = __expf(-bias * bias * inv2s2);
            C[(size_t)r * N_TOK + c] = acc[i][j] * scale + bias;
        }
    }
}

// ---------------- row softmax over 4096 (register-resident) ----------------
__global__ __launch_bounds__(256) void softmax_kernel(float* __restrict__ S)
{
    const int row = blockIdx.x;
    float* __restrict__ p = S + (size_t)row * N_TOK;
    const int tid = threadIdx.x;
    const int lane = tid & 31, warp = tid >> 5;
    __shared__ float red[8];

    float v[16];
    float vmax = -3.4e38f;
#pragma unroll
    for (int i = 0; i < 16; i++) {
        v[i] = p[tid + (i << 8)];
        vmax = fmaxf(vmax, v[i]);
    }
#pragma unroll
    for (int o = 16; o; o >>= 1) vmax = fmaxf(vmax, __shfl_xor_sync(0xffffffffu, vmax, o));
    if (lane == 0) red[warp] = vmax;
    __syncthreads();
    vmax = red[0];
#pragma unroll
    for (int w = 1; w < 8; w++) vmax = fmaxf(vmax, red[w]);
    __syncthreads();

    float sum = 0.0f;
#pragma unroll
    for (int i = 0; i < 16; i++) { v[i] = __expf(v[i] - vmax); sum += v[i]; }
#pragma unroll
    for (int o = 16; o; o >>= 1) sum += __shfl_xor_sync(0xffffffffu, sum, o);
    if (lane == 0) red[warp] = sum;
    __syncthreads();
    sum = red[0];
#pragma unroll
    for (int w = 1; w < 8; w++) sum += red[w];

    const float inv = 1.0f / sum;
#pragma unroll
    for (int i = 0; i < 16; i++) p[tid + (i << 8)] = v[i] * inv;
}

// ---------------- layernorm over 512 (optional fused residual) -------------
__global__ __launch_bounds__(128) void layernorm_kernel(
    const float* __restrict__ X, const float* __restrict__ R,
    const float* __restrict__ g, const float* __restrict__ b,
    float* __restrict__ out)
{
    const int row = blockIdx.x, tid = threadIdx.x;
    const int lane = tid & 31, warp = tid >> 5;
    __shared__ float red[4];

    float4 x = ((const float4*)(X + (size_t)row * D_DIM))[tid];
    if (R) {
        float4 r = ((const float4*)(R + (size_t)row * D_DIM))[tid];
        x.x += r.x; x.y += r.y; x.z += r.z; x.w += r.w;
    }
    float s = x.x + x.y + x.z + x.w;
#pragma unroll
    for (int o = 16; o; o >>= 1) s += __shfl_xor_sync(0xffffffffu, s, o);
    if (lane == 0) red[warp] = s;
    __syncthreads();
    s = red[0] + red[1] + red[2] + red[3];
    const float mean = s * (1.0f / (float)D_DIM);

    const float dx = x.x - mean, dy = x.y - mean, dz = x.z - mean, dw = x.w - mean;
    float q = dx * dx + dy * dy + dz * dz + dw * dw;
    __syncthreads();
#pragma unroll
    for (int o = 16; o; o >>= 1) q += __shfl_xor_sync(0xffffffffu, q, o);
    if (lane == 0) red[warp] = q;
    __syncthreads();
    q = red[0] + red[1] + red[2] + red[3];

    const float rstd = rsqrtf(q * (1.0f / (float)D_DIM) + 1e-5f);
    float4 gg = ((const float4*)g)[tid];
    float4 bb = ((const float4*)b)[tid];
    float4 o4;
    o4.x = dx * rstd * gg.x + bb.x;
    o4.y = dy * rstd * gg.y + bb.y;
    o4.z = dz * rstd * gg.z + bb.z;
    o4.w = dw * rstd * gg.w + bb.w;
    ((float4*)(out + (size_t)row * D_DIM))[tid] = o4;
}

// ---------------- host-side branch driver ----------------------------------
static void run_branch(const float* Qsrc, const float* KVsrc,
                       const float* biasMat, int gauss,
                       const float* WQ, const float* WK, const float* WV,
                       const float* ln1g, const float* ln1b,
                       const float* w1, const float* b1,
                       const float* w2, const float* b2,
                       const float* ln2g, const float* ln2b,
                       float* outp,
                       float* Q, float* K, float* V, float* S,
                       float* X1, float* X2, float* H)
{
    const dim3 gSmall(D_DIM / 64, N_TOK / 64);   // (8, 64)
    const dim3 gScore(N_TOK / 64, N_TOK / 64);   // (64, 64)
    const float scale = 0.04419417382415922f;    // 1/sqrt(512)

    gemm_nn_kernel<<<gSmall, 256>>>(Qsrc, WQ, Q, D_DIM, D_DIM, nullptr, nullptr, 0);
    gemm_nn_kernel<<<gSmall, 256>>>(KVsrc, WK, K, D_DIM, D_DIM, nullptr, nullptr, 0);
    gemm_nn_kernel<<<gSmall, 256>>>(KVsrc, WV, V, D_DIM, D_DIM, nullptr, nullptr, 0);
    gemm_nt_kernel<<<gScore, 256>>>(Q, K, S, D_DIM, scale, biasMat, gauss);
    softmax_kernel<<<N_TOK, 256>>>(S);
    gemm_nn_kernel<<<gSmall, 256>>>(S, V, X1, N_TOK, D_DIM, nullptr, nullptr, 0);
    layernorm_kernel<<<N_TOK, 128>>>(X1, KVsrc, ln1g, ln1b, X2);
    gemm_nn_kernel<<<gSmall, 256>>>(X2, w1, H, D_DIM, D_DIM, b1, nullptr, 1);
    gemm_nn_kernel<<<gSmall, 256>>>(H, w2, X1, D_DIM, D_DIM, b2, X2, 0);
    layernorm_kernel<<<N_TOK, 128>>>(X1, nullptr, ln2g, ln2b, outp);
}

extern "C" void kernel_launch(void* const* d_in, const int* in_sizes, int n_in,
                              void* d_out, int out_size)
{
    (void)in_sizes; (void)n_in; (void)out_size;

    float *Q, *K, *V, *S, *X1, *X2, *H;
    cudaGetSymbolAddress((void**)&Q,  g_Q);
    cudaGetSymbolAddress((void**)&K,  g_K);
    cudaGetSymbolAddress((void**)&V,  g_V);
    cudaGetSymbolAddress((void**)&S,  g_S);
    cudaGetSymbolAddress((void**)&X1, g_X1);
    cudaGetSymbolAddress((void**)&X2, g_X2);
    cudaGetSymbolAddress((void**)&H,  g_H);

    const float* R  = (const float*)d_in[0];
    const float* L  = (const float*)d_in[1];
    const float* Dg = (const float*)d_in[2];
    const float* De = (const float*)d_in[3];

    const float* WQ_r = (const float*)d_in[4];
    const float* WK_r = (const float*)d_in[5];
    const float* WV_r = (const float*)d_in[6];
    const float* ln_r1_g = (const float*)d_in[7];
    const float* ln_r1_b = (const float*)d_in[8];
    const float* ffn_r_w1 = (const float*)d_in[9];
    const float* ffn_r_b1 = (const float*)d_in[10];
    const float* ffn_r_w2 = (const float*)d_in[11];
    const float* ffn_r_b2 = (const float*)d_in[12];
    const float* ln_r2_g = (const float*)d_in[13];
    const float* ln_r2_b = (const float*)d_in[14];

    const float* WQ_l = (const float*)d_in[15];
    const float* WK_l = (const float*)d_in[16];
    const float* WV_l = (const float*)d_in[17];
    const float* ln_l1_g = (const float*)d_in[18];
    const float* ln_l1_b = (const float*)d_in[19];
    const float* ffn_l_w1 = (const float*)d_in[20];
    const float* ffn_l_b1 = (const float*)d_in[21];
    const float* ffn_l_w2 = (const float*)d_in[22];
    const float* ffn_l_b2 = (const float*)d_in[23];
    const float* ln_l2_g = (const float*)d_in[24];
    const float* ln_l2_b = (const float*)d_in[25];

    float* out = (float*)d_out;

    // R branch: Q from L, K/V from R, resid R, Gaussian Euclid bias from De
    run_branch(L, R, De, 1,
               WQ_r, WK_r, WV_r, ln_r1_g, ln_r1_b,
               ffn_r_w1, ffn_r_b1, ffn_r_w2, ffn_r_b2, ln_r2_g, ln_r2_b,
               out, Q, K, V, S, X1, X2, H);

    // L branch: Q from R, K/V from L, resid L, GIoU bias Dg (direct add)
    run_branch(R, L, Dg, 0,
               WQ_l, WK_l, WV_l, ln_l1_g, ln_l1_b,
               ffn_l_w1, ffn_l_b1, ffn_l_w2, ffn_l_b2, ln_l2_g, ln_l2_b,
               out + (size_t)N_TOK * D_DIM, Q, K, V, S, X1, X2, H);
}

// round 3
// speedup vs baseline: 2.6575x; 2.6575x over previous
#include <cuda_runtime.h>
#include <cuda_bf16.h>
#include <cstdint>
#include <math.h>

#define N_TOK 4096
#define D_DIM 512

// ---------------- scratch (device globals; no cudaMalloc allowed) ----------
static __device__ float g_S [(size_t)N_TOK * N_TOK];
static __device__ float g_V [N_TOK * D_DIM];
static __device__ float g_X1[N_TOK * D_DIM];
static __device__ float g_X2[N_TOK * D_DIM];

static __device__ __align__(16) __nv_bfloat16 g_Lh[N_TOK * D_DIM], g_Ll[N_TOK * D_DIM];
static __device__ __align__(16) __nv_bfloat16 g_Rh[N_TOK * D_DIM], g_Rl[N_TOK * D_DIM];
static __device__ __align__(16) __nv_bfloat16 g_Qh[N_TOK * D_DIM], g_Ql[N_TOK * D_DIM];
static __device__ __align__(16) __nv_bfloat16 g_Kh[N_TOK * D_DIM], g_Kl[N_TOK * D_DIM];
static __device__ __align__(16) __nv_bfloat16 g_Vth[N_TOK * D_DIM], g_Vtl[N_TOK * D_DIM];
static __device__ __align__(16) __nv_bfloat16 g_Sh[(size_t)N_TOK * N_TOK], g_Sl[(size_t)N_TOK * N_TOK];
static __device__ __align__(16) __nv_bfloat16 g_X2h[N_TOK * D_DIM], g_X2l[N_TOK * D_DIM];
static __device__ __align__(16) __nv_bfloat16 g_Hh[N_TOK * D_DIM], g_Hl[N_TOK * D_DIM];
static __device__ __align__(16) __nv_bfloat16 g_Wth[5 * D_DIM * D_DIM], g_Wtl[5 * D_DIM * D_DIM];

// ---------------- helpers ---------------------------------------------------
__device__ __forceinline__ uint32_t smem_u32(const void* p) {
    uint32_t a;
    asm("{ .reg .u64 t; cvta.to.shared.u64 t, %1; cvt.u32.u64 %0, t; }" : "=r"(a) : "l"(p));
    return a;
}
__device__ __forceinline__ void cpasync16(uint32_t s, const void* g) {
    asm volatile("cp.async.cg.shared.global [%0], [%1], 16;" :: "r"(s), "l"(g) : "memory");
}
__device__ __forceinline__ void cp_commit() {
    asm volatile("cp.async.commit_group;" ::: "memory");
}
template<int N>
__device__ __forceinline__ void cp_wait() {
    asm volatile("cp.async.wait_group %0;" :: "n"(N) : "memory");
}
__device__ __forceinline__ void ldmx4(uint32_t* r, uint32_t a) {
    asm volatile("ldmatrix.sync.aligned.m8n8.x4.shared.b16 {%0,%1,%2,%3}, [%4];"
                 : "=r"(r[0]), "=r"(r[1]), "=r"(r[2]), "=r"(r[3]) : "r"(a));
}
__device__ __forceinline__ void mma16816(float* c, const uint32_t* a, const uint32_t* b) {
    asm volatile(
        "mma.sync.aligned.m16n8k16.row.col.f32.bf16.bf16.f32 "
        "{%0,%1,%2,%3},{%4,%5,%6,%7},{%8,%9},{%0,%1,%2,%3};"
        : "+f"(c[0]), "+f"(c[1]), "+f"(c[2]), "+f"(c[3])
        : "r"(a[0]), "r"(a[1]), "r"(a[2]), "r"(a[3]), "r"(b[0]), "r"(b[1]));
}
__device__ __forceinline__ void split2(float a, float b, __nv_bfloat162& h, __nv_bfloat162& l) {
    __nv_bfloat16 ha = __float2bfloat16_rn(a), hb = __float2bfloat16_rn(b);
    h.x = ha; h.y = hb;
    l.x = __float2bfloat16_rn(a - __bfloat162float(ha));
    l.y = __float2bfloat16_rn(b - __bfloat162float(hb));
}

// ---------------- elementwise fp32 -> (hi, lo) bf16 split ------------------
__global__ __launch_bounds__(256) void split_kernel(
    const float* __restrict__ in, __nv_bfloat16* __restrict__ oh,
    __nv_bfloat16* __restrict__ ol, int n4)
{
    int i = blockIdx.x * 256 + threadIdx.x;
    if (i >= n4) return;
    float4 v = ((const float4*)in)[i];
    __nv_bfloat162 h0, l0, h1, l1;
    split2(v.x, v.y, h0, l0);
    split2(v.z, v.w, h1, l1);
    ((__nv_bfloat162*)oh)[2 * i]     = h0;
    ((__nv_bfloat162*)oh)[2 * i + 1] = h1;
    ((__nv_bfloat162*)ol)[2 * i]     = l0;
    ((__nv_bfloat162*)ol)[2 * i + 1] = l1;
}

// ---------------- transpose + split: out[c][r] = split(in[r][c]) -----------
__global__ void tconv_kernel(const float* __restrict__ in,
                             __nv_bfloat16* __restrict__ oh,
                             __nv_bfloat16* __restrict__ ol, int rows, int cols)
{
    __shared__ float t[32][33];
    const int bx = blockIdx.x << 5, by = blockIdx.y << 5;
    const int tx = threadIdx.x, ty = threadIdx.y;  // 32 x 8
#pragma unroll
    for (int j = 0; j < 32; j += 8)
        t[ty + j][tx] = in[(size_t)(by + ty + j) * cols + bx + tx];
    __syncthreads();
#pragma unroll
    for (int j = 0; j < 32; j += 8) {
        float v = t[tx][ty + j];
        size_t o = (size_t)(bx + ty + j) * rows + by + tx;
        __nv_bfloat16 h = __float2bfloat16_rn(v);
        oh[o] = h;
        ol[o] = __float2bfloat16_rn(v - __bfloat162float(h));
    }
}

// ---------------- HMMA split-bf16 GEMM: C[M,N] = A[M,K] @ B[N,K]^T ---------
// 128x128x32 CTA tile, 8 warps (2x4), warp tile 64x32, m16n8k16 bf16 mma,
// 3 passes per k-step: Ah*Bh + Ah*Bl + Al*Bh.  Double-buffered cp.async.
enum { EPI_NONE = 0, EPI_GAUSS = 1, EPI_BIAS = 2, EPI_RELU = 3, EPI_RESID = 4 };

#define PADK 40            // padded k-stride in bf16 elems (80 bytes)
#define MAT_ELEMS (128 * PADK)
#define STAGE_BYTES (4 * MAT_ELEMS * 2)
#define SMEM_TOTAL_GEMM (2 * STAGE_BYTES)

template<int EPI, bool SPLIT>
__device__ __forceinline__ void emit2(
    int row, int col, float x, float y, int Ncols,
    const float* __restrict__ bias, const float* __restrict__ resid, float scale,
    float* __restrict__ C, __nv_bfloat16* __restrict__ Oh, __nv_bfloat16* __restrict__ Ol)
{
    if (EPI == EPI_GAUSS) {
        float2 b = *(const float2*)(bias + (size_t)row * Ncols + col);
        x = x * scale + __expf(-b.x * b.x * 0.005f);
        y = y * scale + __expf(-b.y * b.y * 0.005f);
    } else if (EPI == EPI_BIAS) {
        float2 b = *(const float2*)(bias + (size_t)row * Ncols + col);
        x = x * scale + b.x;
        y = y * scale + b.y;
    } else if (EPI == EPI_RELU) {
        float2 b = *(const float2*)(bias + col);
        x = fmaxf(x + b.x, 0.f);
        y = fmaxf(y + b.y, 0.f);
    } else if (EPI == EPI_RESID) {
        float2 b = *(const float2*)(bias + col);
        float2 r = *(const float2*)(resid + (size_t)row * Ncols + col);
        x += b.x + r.x;
        y += b.y + r.y;
    }
    if (SPLIT) {
        __nv_bfloat162 h, l;
        split2(x, y, h, l);
        size_t o = (size_t)row * Ncols + col;
        *(__nv_bfloat162*)(Oh + o) = h;
        *(__nv_bfloat162*)(Ol + o) = l;
    } else {
        float2 v; v.x = x; v.y = y;
        *(float2*)(C + (size_t)row * Ncols + col) = v;
    }
}

template<int EPI, bool SPLIT>
__global__ __launch_bounds__(256, 1) void hmma_gemm(
    const __nv_bfloat16* __restrict__ Ah, const __nv_bfloat16* __restrict__ Al,
    const __nv_bfloat16* __restrict__ Bh, const __nv_bfloat16* __restrict__ Bl,
    float* __restrict__ C, __nv_bfloat16* __restrict__ Oh, __nv_bfloat16* __restrict__ Ol,
    int Kd, int Ncols, const float* __restrict__ bias, const float* __restrict__ resid,
    float scale)
{
    extern __shared__ __align__(16) char smem[];
    const int tid = threadIdx.x;
    const int wid = tid >> 5, lane = tid & 31;
    const int bm = blockIdx.y << 7, bn = blockIdx.x << 7;
    const uint32_t sb = smem_u32(smem);

    // stage s, matrix m (0=Ah,1=Al,2=Bh,3=Bl): offset
    // element offsets
    const uint32_t offAh = 0, offAl = MAT_ELEMS * 2, offBh = MAT_ELEMS * 4, offBl = MAT_ELEMS * 6;

    // per-thread global load coords: 2 chunks per matrix per stage
    const int r0 = tid >> 2, u0 = tid & 3;              // chunk 0: rows 0..63
    const int r1 = (tid + 256) >> 2, u1 = tid & 3;      // chunk 1: rows 64..127

    const int wr = wid >> 2, wc = wid & 3;      // warp 2x4
    const int m0 = wr << 6, n0 = wc << 5;       // warp tile origin (64 x 32)

    float acc[4][4][4];
#pragma unroll
    for (int i = 0; i < 4; i++)
#pragma unroll
        for (int j = 0; j < 4; j++)
#pragma unroll
            for (int q = 0; q < 4; q++) acc[i][j][q] = 0.f;

    const int nIter = Kd >> 5;

    // ldmatrix lane addressing (within warp tile, byte offsets into a matrix)
    const uint32_t a_row = (uint32_t)(m0 + (lane & 15));
    const uint32_t a_colb = (uint32_t)((lane >> 4) << 4);             // 0 or 16 bytes (8 elems)
    const uint32_t b_row = (uint32_t)(n0 + (lane & 7) + ((lane >> 4) << 3));
    const uint32_t b_colb = (uint32_t)(((lane >> 3) & 1) << 4);       // 0 or 16 bytes

    auto load_stage = [&](int it, int buf) {
        const int k0 = it << 5;
        const uint32_t base = sb + (uint32_t)buf * (uint32_t)STAGE_BYTES;
        // A rows
        {
            const __nv_bfloat16* gh = Ah + (size_t)(bm + r0) * Kd + k0 + (u0 << 3);
            const __nv_bfloat16* gl = Al + (size_t)(bm + r0) * Kd + k0 + (u0 << 3);
            uint32_t s = base + (uint32_t)(r0 * 80 + (u0 << 4));
            cpasync16(s + offAh, gh);
            cpasync16(s + offAl, gl);
            const __nv_bfloat16* gh1 = Ah + (size_t)(bm + r1) * Kd + k0 + (u1 << 3);
            const __nv_bfloat16* gl1 = Al + (size_t)(bm + r1) * Kd + k0 + (u1 << 3);
            uint32_t s1 = base + (uint32_t)(r1 * 80 + (u1 << 4));
            cpasync16(s1 + offAh, gh1);
            cpasync16(s1 + offAl, gl1);
        }
        // B rows
        {
            const __nv_bfloat16* gh = Bh + (size_t)(bn + r0) * Kd + k0 + (u0 << 3);
            const __nv_bfloat16* gl = Bl + (size_t)(bn + r0) * Kd + k0 + (u0 << 3);
            uint32_t s = base + (uint32_t)(r0 * 80 + (u0 << 4));
            cpasync16(s + offBh, gh);
            cpasync16(s + offBl, gl);
            const __nv_bfloat16* gh1 = Bh + (size_t)(bn + r1) * Kd + k0 + (u1 << 3);
            const __nv_bfloat16* gl1 = Bl + (size_t)(bn + r1) * Kd + k0 + (u1 << 3);
            uint32_t s1 = base + (uint32_t)(r1 * 80 + (u1 << 4));
            cpasync16(s1 + offBh, gh1);
            cpasync16(s1 + offBl, gl1);
        }
        cp_commit();
    };

    load_stage(0, 0);

    for (int it = 0; it < nIter; it++) {
        if (it + 1 < nIter) {
            load_stage(it + 1, (it + 1) & 1);
            cp_wait<1>();
        } else {
            cp_wait<0>();
        }
        __syncthreads();

        const uint32_t base = sb + (uint32_t)(it & 1) * (uint32_t)STAGE_BYTES;
#pragma unroll
        for (int kk = 0; kk < 2; kk++) {
            const uint32_t kb = (uint32_t)(kk << 5);  // 16 elems = 32 bytes
            uint32_t ah[4][4], al[4][4], bh[4][2], bl[4][2];
#pragma unroll
            for (int i = 0; i < 4; i++) {
                uint32_t ad = base + (a_row + (uint32_t)(i << 4)) * 80u + kb + a_colb;
                ldmx4(ah[i], ad + offAh);
                ldmx4(al[i], ad + offAl);
            }
#pragma unroll
            for (int p = 0; p < 2; p++) {
                uint32_t bd = base + (b_row + (uint32_t)(p << 4)) * 80u + kb + b_colb;
                uint32_t th[4], tl[4];
                ldmx4(th, bd + offBh);
                ldmx4(tl, bd + offBl);
                bh[2 * p][0] = th[0]; bh[2 * p][1] = th[1];
                bh[2 * p + 1][0] = th[2]; bh[2 * p + 1][1] = th[3];
                bl[2 * p][0] = tl[0]; bl[2 * p][1] = tl[1];
                bl[2 * p + 1][0] = tl[2]; bl[2 * p + 1][1] = tl[3];
            }
#pragma unroll
            for (int i = 0; i < 4; i++)
#pragma unroll
                for (int j = 0; j < 4; j++) {
                    mma16816(acc[i][j], ah[i], bh[j]);
                    mma16816(acc[i][j], ah[i], bl[j]);
                    mma16816(acc[i][j], al[i], bh[j]);
                }
        }
        __syncthreads();
    }

    // epilogue
    const int erow = bm + m0 + (lane >> 2);
    const int ecol = bn + n0 + ((lane & 3) << 1);
#pragma unroll
    for (int i = 0; i < 4; i++)
#pragma unroll
        for (int j = 0; j < 4; j++) {
            const int r = erow + (i << 4);
            const int c = ecol + (j << 3);
            emit2<EPI, SPLIT>(r,     c, acc[i][j][0], acc[i][j][1], Ncols, bias, resid, scale, C, Oh, Ol);
            emit2<EPI, SPLIT>(r + 8, c, acc[i][j][2], acc[i][j][3], Ncols, bias, resid, scale, C, Oh, Ol);
        }
}

// ---------------- row softmax over 4096 ------------------------------------
__global__ __launch_bounds__(256) void softmax_kernel(float* __restrict__ S)
{
    const int row = blockIdx.x;
    float* __restrict__ p = S + (size_t)row * N_TOK;
    const int tid = threadIdx.x;
    const int lane = tid & 31, warp = tid >> 5;
    __shared__ float red[8];

    float v[16];
    float vmax = -3.4e38f;
#pragma unroll
    for (int i = 0; i < 16; i++) {
        v[i] = p[tid + (i << 8)];
        vmax = fmaxf(vmax, v[i]);
    }
#pragma unroll
    for (int o = 16; o; o >>= 1) vmax = fmaxf(vmax, __shfl_xor_sync(0xffffffffu, vmax, o));
    if (lane == 0) red[warp] = vmax;
    __syncthreads();
    vmax = red[0];
#pragma unroll
    for (int w = 1; w < 8; w++) vmax = fmaxf(vmax, red[w]);
    __syncthreads();

    float sum = 0.0f;
#pragma unroll
    for (int i = 0; i < 16; i++) { v[i] = __expf(v[i] - vmax); sum += v[i]; }
#pragma unroll
    for (int o = 16; o; o >>= 1) sum += __shfl_xor_sync(0xffffffffu, sum, o);
    if (lane == 0) red[warp] = sum;
    __syncthreads();
    sum = red[0];
#pragma unroll
    for (int w = 1; w < 8; w++) sum += red[w];

    const float inv = 1.0f / sum;
#pragma unroll
    for (int i = 0; i < 16; i++) p[tid + (i << 8)] = v[i] * inv;
}

// ---------------- layernorm over 512 (optional resid, optional split out) --
__global__ __launch_bounds__(128) void layernorm_kernel(
    const float* __restrict__ X, const float* __restrict__ R,
    const float* __restrict__ g, const float* __restrict__ b,
    float* __restrict__ out, __nv_bfloat16* __restrict__ oh, __nv_bfloat16* __restrict__ ol)
{
    const int row = blockIdx.x, tid = threadIdx.x;
    const int lane = tid & 31, warp = tid >> 5;
    __shared__ float red[4];

    float4 x = ((const float4*)(X + (size_t)row * D_DIM))[tid];
    if (R) {
        float4 r = ((const float4*)(R + (size_t)row * D_DIM))[tid];
        x.x += r.x; x.y += r.y; x.z += r.z; x.w += r.w;
    }
    float s = x.x + x.y + x.z + x.w;
#pragma unroll
    for (int o = 16; o; o >>= 1) s += __shfl_xor_sync(0xffffffffu, s, o);
    if (lane == 0) red[warp] = s;
    __syncthreads();
    s = red[0] + red[1] + red[2] + red[3];
    const float mean = s * (1.0f / (float)D_DIM);

    const float dx = x.x - mean, dy = x.y - mean, dz = x.z - mean, dw = x.w - mean;
    float q = dx * dx + dy * dy + dz * dz + dw * dw;
    __syncthreads();
#pragma unroll
    for (int o = 16; o; o >>= 1) q += __shfl_xor_sync(0xffffffffu, q, o);
    if (lane == 0) red[warp] = q;
    __syncthreads();
    q = red[0] + red[1] + red[2] + red[3];

    const float rstd = rsqrtf(q * (1.0f / (float)D_DIM) + 1e-5f);
    float4 gg = ((const float4*)g)[tid];
    float4 bb = ((const float4*)b)[tid];
    float4 o4;
    o4.x = dx * rstd * gg.x + bb.x;
    o4.y = dy * rstd * gg.y + bb.y;
    o4.z = dz * rstd * gg.z + bb.z;
    o4.w = dw * rstd * gg.w + bb.w;
    ((float4*)(out + (size_t)row * D_DIM))[tid] = o4;
    if (oh) {
        __nv_bfloat162 h0, l0, h1, l1;
        split2(o4.x, o4.y, h0, l0);
        split2(o4.z, o4.w, h1, l1);
        size_t o = (size_t)row * D_DIM + tid * 4;
        *(__nv_bfloat162*)(oh + o)     = h0;
        *(__nv_bfloat162*)(oh + o + 2) = h1;
        *(__nv_bfloat162*)(ol + o)     = l0;
        *(__nv_bfloat162*)(ol + o + 2) = l1;
    }
}

// ---------------- host side -------------------------------------------------
struct Scratch {
    float *S, *V, *X1, *X2;
    __nv_bfloat16 *Lh, *Ll, *Rh, *Rl, *Qh, *Ql, *Kh, *Kl, *Vth, *Vtl;
    __nv_bfloat16 *Sh, *Sl, *X2h, *X2l, *Hh, *Hl, *Wth, *Wtl;
};

static void get_scratch(Scratch& s) {
    cudaGetSymbolAddress((void**)&s.S,  g_S);
    cudaGetSymbolAddress((void**)&s.V,  g_V);
    cudaGetSymbolAddress((void**)&s.X1, g_X1);
    cudaGetSymbolAddress((void**)&s.X2, g_X2);
    cudaGetSymbolAddress((void**)&s.Lh, g_Lh);   cudaGetSymbolAddress((void**)&s.Ll, g_Ll);
    cudaGetSymbolAddress((void**)&s.Rh, g_Rh);   cudaGetSymbolAddress((void**)&s.Rl, g_Rl);
    cudaGetSymbolAddress((void**)&s.Qh, g_Qh);   cudaGetSymbolAddress((void**)&s.Ql, g_Ql);
    cudaGetSymbolAddress((void**)&s.Kh, g_Kh);   cudaGetSymbolAddress((void**)&s.Kl, g_Kl);
    cudaGetSymbolAddress((void**)&s.Vth, g_Vth); cudaGetSymbolAddress((void**)&s.Vtl, g_Vtl);
    cudaGetSymbolAddress((void**)&s.Sh, g_Sh);   cudaGetSymbolAddress((void**)&s.Sl, g_Sl);
    cudaGetSymbolAddress((void**)&s.X2h, g_X2h); cudaGetSymbolAddress((void**)&s.X2l, g_X2l);
    cudaGetSymbolAddress((void**)&s.Hh, g_Hh);   cudaGetSymbolAddress((void**)&s.Hl, g_Hl);
    cudaGetSymbolAddress((void**)&s.Wth, g_Wth); cudaGetSymbolAddress((void**)&s.Wtl, g_Wtl);
}

static void set_attrs() {
    cudaFuncSetAttribute((const void*)hmma_gemm<EPI_NONE,  true >, cudaFuncAttributeMaxDynamicSharedMemorySize, SMEM_TOTAL_GEMM);
    cudaFuncSetAttribute((const void*)hmma_gemm<EPI_NONE,  false>, cudaFuncAttributeMaxDynamicSharedMemorySize, SMEM_TOTAL_GEMM);
    cudaFuncSetAttribute((const void*)hmma_gemm<EPI_GAUSS, false>, cudaFuncAttributeMaxDynamicSharedMemorySize, SMEM_TOTAL_GEMM);
    cudaFuncSetAttribute((const void*)hmma_gemm<EPI_BIAS,  false>, cudaFuncAttributeMaxDynamicSharedMemorySize, SMEM_TOTAL_GEMM);
    cudaFuncSetAttribute((const void*)hmma_gemm<EPI_RELU,  true >, cudaFuncAttributeMaxDynamicSharedMemorySize, SMEM_TOTAL_GEMM);
    cudaFuncSetAttribute((const void*)hmma_gemm<EPI_RESID, false>, cudaFuncAttributeMaxDynamicSharedMemorySize, SMEM_TOTAL_GEMM);
}

static void run_branch(const Scratch& s,
                       const __nv_bfloat16* Qh_src, const __nv_bfloat16* Ql_src,
                       const __nv_bfloat16* KVh_src, const __nv_bfloat16* KVl_src,
                       const float* KV_f32, const float* biasMat, int gauss,
                       const float* WQ, const float* WK, const float* WV,
                       const float* ln1g, const float* ln1b,
                       const float* w1, const float* b1,
                       const float* w2, const float* b2,
                       const float* ln2g, const float* ln2b,
                       float* outp)
{
    const dim3 tW(16, 16), tB(32, 8);
    const int WSZ = D_DIM * D_DIM;
    const float scale = 0.04419417382415922f;  // 1/sqrt(512)

    // transpose+split the five weight matrices
    tconv_kernel<<<tW, tB>>>(WQ, s.Wth + 0 * WSZ, s.Wtl + 0 * WSZ, D_DIM, D_DIM);
    tconv_kernel<<<tW, tB>>>(WK, s.Wth + 1 * WSZ, s.Wtl + 1 * WSZ, D_DIM, D_DIM);
    tconv_kernel<<<tW, tB>>>(WV, s.Wth + 2 * WSZ, s.Wtl + 2 * WSZ, D_DIM, D_DIM);
    tconv_kernel<<<tW, tB>>>(w1, s.Wth + 3 * WSZ, s.Wtl + 3 * WSZ, D_DIM, D_DIM);
    tconv_kernel<<<tW, tB>>>(w2, s.Wth + 4 * WSZ, s.Wtl + 4 * WSZ, D_DIM, D_DIM);

    const dim3 gP(D_DIM / 128, N_TOK / 128);   // (4, 32)
    const dim3 gS(N_TOK / 128, N_TOK / 128);   // (32, 32)

    // projections
    hmma_gemm<EPI_NONE, true><<<gP, 256, SMEM_TOTAL_GEMM>>>(
        Qh_src, Ql_src, s.Wth + 0 * WSZ, s.Wtl + 0 * WSZ,
        nullptr, s.Qh, s.Ql, D_DIM, D_DIM, nullptr, nullptr, 0.f);
    hmma_gemm<EPI_NONE, true><<<gP, 256, SMEM_TOTAL_GEMM>>>(
        KVh_src, KVl_src, s.Wth + 1 * WSZ, s.Wtl + 1 * WSZ,
        nullptr, s.Kh, s.Kl, D_DIM, D_DIM, nullptr, nullptr, 0.f);
    hmma_gemm<EPI_NONE, false><<<gP, 256, SMEM_TOTAL_GEMM>>>(
        KVh_src, KVl_src, s.Wth + 2 * WSZ, s.Wtl + 2 * WSZ,
        s.V, nullptr, nullptr, D_DIM, D_DIM, nullptr, nullptr, 0.f);
    tconv_kernel<<<dim3(16, 128), tB>>>(s.V, s.Vth, s.Vtl, N_TOK, D_DIM);

    // scores + softmax + split
    if (gauss)
        hmma_gemm<EPI_GAUSS, false><<<gS, 256, SMEM_TOTAL_GEMM>>>(
            s.Qh, s.Ql, s.Kh, s.Kl, s.S, nullptr, nullptr, D_DIM, N_TOK, biasMat, nullptr, scale);
    else
        hmma_gemm<EPI_BIAS, false><<<gS, 256, SMEM_TOTAL_GEMM>>>(
            s.Qh, s.Ql, s.Kh, s.Kl, s.S, nullptr, nullptr, D_DIM, N_TOK, biasMat, nullptr, scale);
    softmax_kernel<<<N_TOK, 256>>>(s.S);
    split_kernel<<<(N_TOK * (N_TOK / 4)) / 256, 256>>>(s.S, s.Sh, s.Sl, N_TOK * (N_TOK / 4));

    // att @ V
    hmma_gemm<EPI_NONE, false><<<gP, 256, SMEM_TOTAL_GEMM>>>(
        s.Sh, s.Sl, s.Vth, s.Vtl, s.X1, nullptr, nullptr, N_TOK, D_DIM, nullptr, nullptr, 0.f);
    layernorm_kernel<<<N_TOK, 128>>>(s.X1, KV_f32, ln1g, ln1b, s.X2, s.X2h, s.X2l);

    // FFN
    hmma_gemm<EPI_RELU, true><<<gP, 256, SMEM_TOTAL_GEMM>>>(
        s.X2h, s.X2l, s.Wth + 3 * WSZ, s.Wtl + 3 * WSZ,
        nullptr, s.Hh, s.Hl, D_DIM, D_DIM, b1, nullptr, 0.f);
    hmma_gemm<EPI_RESID, false><<<gP, 256, SMEM_TOTAL_GEMM>>>(
        s.Hh, s.Hl, s.Wth + 4 * WSZ, s.Wtl + 4 * WSZ,
        s.X1, nullptr, nullptr, D_DIM, D_DIM, b2, s.X2, 0.f);
    layernorm_kernel<<<N_TOK, 128>>>(s.X1, nullptr, ln2g, ln2b, outp, nullptr, nullptr);
}

extern "C" void kernel_launch(void* const* d_in, const int* in_sizes, int n_in,
                              void* d_out, int out_size)
{
    (void)in_sizes; (void)n_in; (void)out_size;
    Scratch s;
    get_scratch(s);
    set_attrs();

    const float* R  = (const float*)d_in[0];
    const float* L  = (const float*)d_in[1];
    const float* Dg = (const float*)d_in[2];
    const float* De = (const float*)d_in[3];

    const float* WQ_r = (const float*)d_in[4];
    const float* WK_r = (const float*)d_in[5];
    const float* WV_r = (const float*)d_in[6];
    const float* ln_r1_g = (const float*)d_in[7];
    const float* ln_r1_b = (const float*)d_in[8];
    const float* ffn_r_w1 = (const float*)d_in[9];
    const float* ffn_r_b1 = (const float*)d_in[10];
    const float* ffn_r_w2 = (const float*)d_in[11];
    const float* ffn_r_b2 = (const float*)d_in[12];
    const float* ln_r2_g = (const float*)d_in[13];
    const float* ln_r2_b = (const float*)d_in[14];

    const float* WQ_l = (const float*)d_in[15];
    const float* WK_l = (const float*)d_in[16];
    const float* WV_l = (const float*)d_in[17];
    const float* ln_l1_g = (const float*)d_in[18];
    const float* ln_l1_b = (const float*)d_in[19];
    const float* ffn_l_w1 = (const float*)d_in[20];
    const float* ffn_l_b1 = (const float*)d_in[21];
    const float* ffn_l_w2 = (const float*)d_in[22];
    const float* ffn_l_b2 = (const float*)d_in[23];
    const float* ln_l2_g = (const float*)d_in[24];
    const float* ln_l2_b = (const float*)d_in[25];

    float* out = (float*)d_out;

    // split the two token matrices once
    const int n4 = N_TOK * D_DIM / 4;
    split_kernel<<<n4 / 256, 256>>>(L, s.Lh, s.Ll, n4);
    split_kernel<<<n4 / 256, 256>>>(R, s.Rh, s.Rl, n4);

    // R branch: Q from L, K/V from R, resid R, Gaussian bias from De
    run_branch(s, s.Lh, s.Ll, s.Rh, s.Rl, R, De, 1,
               WQ_r, WK_r, WV_r, ln_r1_g, ln_r1_b,
               ffn_r_w1, ffn_r_b1, ffn_r_w2, ffn_r_b2, ln_r2_g, ln_r2_b,
               out);

    // L branch: Q from R, K/V from L, resid L, bias Dg (direct add)
    run_branch(s, s.Rh, s.Rl, s.Lh, s.Ll, L, Dg, 0,
               WQ_l, WK_l, WV_l, ln_l1_g, ln_l1_b,
               ffn_l_w1, ffn_l_b1, ffn_l_w2, ffn_l_b2, ln_l2_g, ln_l2_b,
               out + (size_t)N_TOK * D_DIM);
}

// round 4
// speedup vs baseline: 2.7572x; 1.0375x over previous
#include <cuda_runtime.h>
#include <cuda_bf16.h>
#include <cstdint>
#include <math.h>

#define N_TOK 4096
#define D_DIM 512

// ---------------- scratch (device globals; no cudaMalloc allowed) ----------
static __device__ float g_S [(size_t)N_TOK * N_TOK];
static __device__ float g_V [N_TOK * D_DIM];
static __device__ float g_X1[N_TOK * D_DIM];
static __device__ float g_X2[N_TOK * D_DIM];

static __device__ __align__(16) __nv_bfloat16 g_Lh[N_TOK * D_DIM], g_Ll[N_TOK * D_DIM];
static __device__ __align__(16) __nv_bfloat16 g_Rh[N_TOK * D_DIM], g_Rl[N_TOK * D_DIM];
static __device__ __align__(16) __nv_bfloat16 g_Qh[N_TOK * D_DIM], g_Ql[N_TOK * D_DIM];
static __device__ __align__(16) __nv_bfloat16 g_Kh[N_TOK * D_DIM], g_Kl[N_TOK * D_DIM];
static __device__ __align__(16) __nv_bfloat16 g_Vth[N_TOK * D_DIM], g_Vtl[N_TOK * D_DIM];
static __device__ __align__(16) __nv_bfloat16 g_Sh[(size_t)N_TOK * N_TOK], g_Sl[(size_t)N_TOK * N_TOK];
static __device__ __align__(16) __nv_bfloat16 g_X2h[N_TOK * D_DIM], g_X2l[N_TOK * D_DIM];
static __device__ __align__(16) __nv_bfloat16 g_Hh[N_TOK * D_DIM], g_Hl[N_TOK * D_DIM];
static __device__ __align__(16) __nv_bfloat16 g_Wth[5 * D_DIM * D_DIM], g_Wtl[5 * D_DIM * D_DIM];

// ---------------- helpers ---------------------------------------------------
__device__ __forceinline__ uint32_t smem_u32(const void* p) {
    uint32_t a;
    asm("{ .reg .u64 t; cvta.to.shared.u64 t, %1; cvt.u32.u64 %0, t; }" : "=r"(a) : "l"(p));
    return a;
}
__device__ __forceinline__ void cpasync16(uint32_t s, const void* g) {
    asm volatile("cp.async.cg.shared.global [%0], [%1], 16;" :: "r"(s), "l"(g) : "memory");
}
__device__ __forceinline__ void cp_commit() {
    asm volatile("cp.async.commit_group;" ::: "memory");
}
template<int N>
__device__ __forceinline__ void cp_wait() {
    asm volatile("cp.async.wait_group %0;" :: "n"(N) : "memory");
}
__device__ __forceinline__ void ldmx4(uint32_t* r, uint32_t a) {
    asm volatile("ldmatrix.sync.aligned.m8n8.x4.shared.b16 {%0,%1,%2,%3}, [%4];"
                 : "=r"(r[0]), "=r"(r[1]), "=r"(r[2]), "=r"(r[3]) : "r"(a));
}
__device__ __forceinline__ void mma16816(float* c, const uint32_t* a, const uint32_t* b) {
    asm volatile(
        "mma.sync.aligned.m16n8k16.row.col.f32.bf16.bf16.f32 "
        "{%0,%1,%2,%3},{%4,%5,%6,%7},{%8,%9},{%0,%1,%2,%3};"
        : "+f"(c[0]), "+f"(c[1]), "+f"(c[2]), "+f"(c[3])
        : "r"(a[0]), "r"(a[1]), "r"(a[2]), "r"(a[3]), "r"(b[0]), "r"(b[1]));
}
__device__ __forceinline__ void split2(float a, float b, __nv_bfloat162& h, __nv_bfloat162& l) {
    __nv_bfloat16 ha = __float2bfloat16_rn(a), hb = __float2bfloat16_rn(b);
    h.x = ha; h.y = hb;
    l.x = __float2bfloat16_rn(a - __bfloat162float(ha));
    l.y = __float2bfloat16_rn(b - __bfloat162float(hb));
}

// ---------------- elementwise fp32 -> (hi, lo) bf16 split ------------------
__global__ __launch_bounds__(256) void split_kernel(
    const float* __restrict__ in, __nv_bfloat16* __restrict__ oh,
    __nv_bfloat16* __restrict__ ol, int n4)
{
    int i = blockIdx.x * 256 + threadIdx.x;
    if (i >= n4) return;
    float4 v = ((const float4*)in)[i];
    __nv_bfloat162 h0, l0, h1, l1;
    split2(v.x, v.y, h0, l0);
    split2(v.z, v.w, h1, l1);
    ((__nv_bfloat162*)oh)[2 * i]     = h0;
    ((__nv_bfloat162*)oh)[2 * i + 1] = h1;
    ((__nv_bfloat162*)ol)[2 * i]     = l0;
    ((__nv_bfloat162*)ol)[2 * i + 1] = l1;
}

// ---------------- transpose + split: out[c][r] = split(in[r][c]) -----------
__global__ void tconv_kernel(const float* __restrict__ in,
                             __nv_bfloat16* __restrict__ oh,
                             __nv_bfloat16* __restrict__ ol, int rows, int cols)
{
    __shared__ float t[32][33];
    const int bx = blockIdx.x << 5, by = blockIdx.y << 5;
    const int tx = threadIdx.x, ty = threadIdx.y;  // 32 x 8
#pragma unroll
    for (int j = 0; j < 32; j += 8)
        t[ty + j][tx] = in[(size_t)(by + ty + j) * cols + bx + tx];
    __syncthreads();
#pragma unroll
    for (int j = 0; j < 32; j += 8) {
        float v = t[tx][ty + j];
        size_t o = (size_t)(bx + ty + j) * rows + by + tx;
        __nv_bfloat16 h = __float2bfloat16_rn(v);
        oh[o] = h;
        ol[o] = __float2bfloat16_rn(v - __bfloat162float(h));
    }
}

// ---------------- HMMA split-bf16 GEMM: C[M,N] = A[M,K] @ B[N,K]^T ---------
// 128x128x32 CTA tile, 8 warps (2x4), warp tile 64x32, m16n8k16 bf16 mma,
// 3 passes per k-step: Ah*Bh + Ah*Bl + Al*Bh.  3-stage cp.async pipeline.
enum { EPI_NONE = 0, EPI_GAUSS = 1, EPI_BIAS = 2, EPI_RELU = 3, EPI_RESID = 4 };

#define PADK 40            // padded k-stride in bf16 elems (80 bytes)
#define MAT_ELEMS (128 * PADK)
#define STAGE_BYTES (4 * MAT_ELEMS * 2)
#define NSTAGE 3
#define SMEM_TOTAL_GEMM (NSTAGE * STAGE_BYTES)

template<int EPI, bool SPLIT>
__device__ __forceinline__ void emit2(
    int row, int col, float x, float y, int Ncols,
    const float* __restrict__ bias, const float* __restrict__ resid, float scale,
    float* __restrict__ C, __nv_bfloat16* __restrict__ Oh, __nv_bfloat16* __restrict__ Ol)
{
    if (EPI == EPI_GAUSS) {
        float2 b = *(const float2*)(bias + (size_t)row * Ncols + col);
        x = x * scale + __expf(-b.x * b.x * 0.005f);
        y = y * scale + __expf(-b.y * b.y * 0.005f);
    } else if (EPI == EPI_BIAS) {
        float2 b = *(const float2*)(bias + (size_t)row * Ncols + col);
        x = x * scale + b.x;
        y = y * scale + b.y;
    } else if (EPI == EPI_RELU) {
        float2 b = *(const float2*)(bias + col);
        x = fmaxf(x + b.x, 0.f);
        y = fmaxf(y + b.y, 0.f);
    } else if (EPI == EPI_RESID) {
        float2 b = *(const float2*)(bias + col);
        float2 r = *(const float2*)(resid + (size_t)row * Ncols + col);
        x += b.x + r.x;
        y += b.y + r.y;
    }
    if (SPLIT) {
        __nv_bfloat162 h, l;
        split2(x, y, h, l);
        size_t o = (size_t)row * Ncols + col;
        *(__nv_bfloat162*)(Oh + o) = h;
        *(__nv_bfloat162*)(Ol + o) = l;
    } else {
        float2 v; v.x = x; v.y = y;
        *(float2*)(C + (size_t)row * Ncols + col) = v;
    }
}

template<int EPI, bool SPLIT>
__global__ __launch_bounds__(256, 1) void hmma_gemm(
    const __nv_bfloat16* __restrict__ Ah, const __nv_bfloat16* __restrict__ Al,
    const __nv_bfloat16* __restrict__ Bh, const __nv_bfloat16* __restrict__ Bl,
    float* __restrict__ C, __nv_bfloat16* __restrict__ Oh, __nv_bfloat16* __restrict__ Ol,
    int Kd, int Ncols, const float* __restrict__ bias, const float* __restrict__ resid,
    float scale)
{
    extern __shared__ __align__(16) char smem[];
    const int tid = threadIdx.x;
    const int wid = tid >> 5, lane = tid & 31;
    const int bm = blockIdx.y << 7, bn = blockIdx.x << 7;
    const uint32_t sb = smem_u32(smem);

    const uint32_t offAh = 0, offAl = MAT_ELEMS * 2, offBh = MAT_ELEMS * 4, offBl = MAT_ELEMS * 6;

    const int r0 = tid >> 2, u0 = tid & 3;              // chunk 0: rows 0..63
    const int r1 = (tid + 256) >> 2, u1 = tid & 3;      // chunk 1: rows 64..127

    const int wr = wid >> 2, wc = wid & 3;      // warp 2x4
    const int m0 = wr << 6, n0 = wc << 5;       // warp tile origin (64 x 32)

    float acc[4][4][4];
#pragma unroll
    for (int i = 0; i < 4; i++)
#pragma unroll
        for (int j = 0; j < 4; j++)
#pragma unroll
            for (int q = 0; q < 4; q++) acc[i][j][q] = 0.f;

    const int nIter = Kd >> 5;

    const uint32_t a_row = (uint32_t)(m0 + (lane & 15));
    const uint32_t a_colb = (uint32_t)((lane >> 4) << 4);
    const uint32_t b_row = (uint32_t)(n0 + (lane & 7) + ((lane >> 4) << 3));
    const uint32_t b_colb = (uint32_t)(((lane >> 3) & 1) << 4);

    auto load_stage = [&](int it, int buf) {
        const int k0 = it << 5;
        const uint32_t base = sb + (uint32_t)buf * (uint32_t)STAGE_BYTES;
        {
            uint32_t s = base + (uint32_t)(r0 * 80 + (u0 << 4));
            cpasync16(s + offAh, Ah + (size_t)(bm + r0) * Kd + k0 + (u0 << 3));
            cpasync16(s + offAl, Al + (size_t)(bm + r0) * Kd + k0 + (u0 << 3));
            uint32_t s1 = base + (uint32_t)(r1 * 80 + (u1 << 4));
            cpasync16(s1 + offAh, Ah + (size_t)(bm + r1) * Kd + k0 + (u1 << 3));
            cpasync16(s1 + offAl, Al + (size_t)(bm + r1) * Kd + k0 + (u1 << 3));
        }
        {
            uint32_t s = base + (uint32_t)(r0 * 80 + (u0 << 4));
            cpasync16(s + offBh, Bh + (size_t)(bn + r0) * Kd + k0 + (u0 << 3));
            cpasync16(s + offBl, Bl + (size_t)(bn + r0) * Kd + k0 + (u0 << 3));
            uint32_t s1 = base + (uint32_t)(r1 * 80 + (u1 << 4));
            cpasync16(s1 + offBh, Bh + (size_t)(bn + r1) * Kd + k0 + (u1 << 3));
            cpasync16(s1 + offBl, Bl + (size_t)(bn + r1) * Kd + k0 + (u1 << 3));
        }
    };

    // prologue: stages 0 and 1 in flight
    load_stage(0, 0); cp_commit();
    if (nIter > 1) load_stage(1, 1);
    cp_commit();

    int buf = 0;
    for (int it = 0; it < nIter; it++) {
        // keep 3rd stage in flight; always commit so group count stays uniform
        if (it + 2 < nIter) load_stage(it + 2, (buf + 2) % NSTAGE);
        cp_commit();
        cp_wait<2>();           // stage `it` resident
        __syncthreads();

        const uint32_t base = sb + (uint32_t)buf * (uint32_t)STAGE_BYTES;
#pragma unroll
        for (int kk = 0; kk < 2; kk++) {
            const uint32_t kb = (uint32_t)(kk << 5);
            uint32_t ah[4][4], al[4][4], bh[4][2], bl[4][2];
#pragma unroll
            for (int i = 0; i < 4; i++) {
                uint32_t ad = base + (a_row + (uint32_t)(i << 4)) * 80u + kb + a_colb;
                ldmx4(ah[i], ad + offAh);
                ldmx4(al[i], ad + offAl);
            }
#pragma unroll
            for (int p = 0; p < 2; p++) {
                uint32_t bd = base + (b_row + (uint32_t)(p << 4)) * 80u + kb + b_colb;
                uint32_t th[4], tl[4];
                ldmx4(th, bd + offBh);
                ldmx4(tl, bd + offBl);
                bh[2 * p][0] = th[0]; bh[2 * p][1] = th[1];
                bh[2 * p + 1][0] = th[2]; bh[2 * p + 1][1] = th[3];
                bl[2 * p][0] = tl[0]; bl[2 * p][1] = tl[1];
                bl[2 * p + 1][0] = tl[2]; bl[2 * p + 1][1] = tl[3];
            }
#pragma unroll
            for (int i = 0; i < 4; i++)
#pragma unroll
                for (int j = 0; j < 4; j++) {
                    mma16816(acc[i][j], ah[i], bh[j]);
                    mma16816(acc[i][j], ah[i], bl[j]);
                    mma16816(acc[i][j], al[i], bh[j]);
                }
        }
        __syncthreads();
        buf = (buf + 1) % NSTAGE;
    }

    // epilogue
    const int erow = bm + m0 + (lane >> 2);
    const int ecol = bn + n0 + ((lane & 3) << 1);
#pragma unroll
    for (int i = 0; i < 4; i++)
#pragma unroll
        for (int j = 0; j < 4; j++) {
            const int r = erow + (i << 4);
            const int c = ecol + (j << 3);
            emit2<EPI, SPLIT>(r,     c, acc[i][j][0], acc[i][j][1], Ncols, bias, resid, scale, C, Oh, Ol);
            emit2<EPI, SPLIT>(r + 8, c, acc[i][j][2], acc[i][j][3], Ncols, bias, resid, scale, C, Oh, Ol);
        }
}

// ---------------- row softmax over 4096, fused bf16 hi/lo split output -----
__global__ __launch_bounds__(256) void softmax_split_kernel(
    const float* __restrict__ S, __nv_bfloat16* __restrict__ Sh,
    __nv_bfloat16* __restrict__ Sl)
{
    const int row = blockIdx.x;
    const float* __restrict__ p = S + (size_t)row * N_TOK;
    const int tid = threadIdx.x;
    const int lane = tid & 31, warp = tid >> 5;
    __shared__ float red[8];

    float v[16];
    float vmax = -3.4e38f;
#pragma unroll
    for (int i = 0; i < 16; i++) {
        v[i] = p[tid + (i << 8)];
        vmax = fmaxf(vmax, v[i]);
    }
#pragma unroll
    for (int o = 16; o; o >>= 1) vmax = fmaxf(vmax, __shfl_xor_sync(0xffffffffu, vmax, o));
    if (lane == 0) red[warp] = vmax;
    __syncthreads();
    vmax = red[0];
#pragma unroll
    for (int w = 1; w < 8; w++) vmax = fmaxf(vmax, red[w]);
    __syncthreads();

    float sum = 0.0f;
#pragma unroll
    for (int i = 0; i < 16; i++) { v[i] = __expf(v[i] - vmax); sum += v[i]; }
#pragma unroll
    for (int o = 16; o; o >>= 1) sum += __shfl_xor_sync(0xffffffffu, sum, o);
    if (lane == 0) red[warp] = sum;
    __syncthreads();
    sum = red[0];
#pragma unroll
    for (int w = 1; w < 8; w++) sum += red[w];

    const float inv = 1.0f / sum;
    __nv_bfloat16* __restrict__ ph = Sh + (size_t)row * N_TOK;
    __nv_bfloat16* __restrict__ pl = Sl + (size_t)row * N_TOK;
#pragma unroll
    for (int i = 0; i < 16; i += 2) {
        float a = v[i] * inv, b = v[i + 1] * inv;  // cols tid+i*256, tid+(i+1)*256
        __nv_bfloat16 ha = __float2bfloat16_rn(a), hb = __float2bfloat16_rn(b);
        ph[tid + (i << 8)]       = ha;
        ph[tid + ((i + 1) << 8)] = hb;
        pl[tid + (i << 8)]       = __float2bfloat16_rn(a - __bfloat162float(ha));
        pl[tid + ((i + 1) << 8)] = __float2bfloat16_rn(b - __bfloat162float(hb));
    }
}

// ---------------- layernorm over 512 (optional resid, optional split out) --
__global__ __launch_bounds__(128) void layernorm_kernel(
    const float* __restrict__ X, const float* __restrict__ R,
    const float* __restrict__ g, const float* __restrict__ b,
    float* __restrict__ out, __nv_bfloat16* __restrict__ oh, __nv_bfloat16* __restrict__ ol)
{
    const int row = blockIdx.x, tid = threadIdx.x;
    const int lane = tid & 31, warp = tid >> 5;
    __shared__ float red[4];

    float4 x = ((const float4*)(X + (size_t)row * D_DIM))[tid];
    if (R) {
        float4 r = ((const float4*)(R + (size_t)row * D_DIM))[tid];
        x.x += r.x; x.y += r.y; x.z += r.z; x.w += r.w;
    }
    float s = x.x + x.y + x.z + x.w;
#pragma unroll
    for (int o = 16; o; o >>= 1) s += __shfl_xor_sync(0xffffffffu, s, o);
    if (lane == 0) red[warp] = s;
    __syncthreads();
    s = red[0] + red[1] + red[2] + red[3];
    const float mean = s * (1.0f / (float)D_DIM);

    const float dx = x.x - mean, dy = x.y - mean, dz = x.z - mean, dw = x.w - mean;
    float q = dx * dx + dy * dy + dz * dz + dw * dw;
    __syncthreads();
#pragma unroll
    for (int o = 16; o; o >>= 1) q += __shfl_xor_sync(0xffffffffu, q, o);
    if (lane == 0) red[warp] = q;
    __syncthreads();
    q = red[0] + red[1] + red[2] + red[3];

    const float rstd = rsqrtf(q * (1.0f / (float)D_DIM) + 1e-5f);
    float4 gg = ((const float4*)g)[tid];
    float4 bb = ((const float4*)b)[tid];
    float4 o4;
    o4.x = dx * rstd * gg.x + bb.x;
    o4.y = dy * rstd * gg.y + bb.y;
    o4.z = dz * rstd * gg.z + bb.z;
    o4.w = dw * rstd * gg.w + bb.w;
    ((float4*)(out + (size_t)row * D_DIM))[tid] = o4;
    if (oh) {
        __nv_bfloat162 h0, l0, h1, l1;
        split2(o4.x, o4.y, h0, l0);
        split2(o4.z, o4.w, h1, l1);
        size_t o = (size_t)row * D_DIM + tid * 4;
        *(__nv_bfloat162*)(oh + o)     = h0;
        *(__nv_bfloat162*)(oh + o + 2) = h1;
        *(__nv_bfloat162*)(ol + o)     = l0;
        *(__nv_bfloat162*)(ol + o + 2) = l1;
    }
}

// ---------------- host side -------------------------------------------------
struct Scratch {
    float *S, *V, *X1, *X2;
    __nv_bfloat16 *Lh, *Ll, *Rh, *Rl, *Qh, *Ql, *Kh, *Kl, *Vth, *Vtl;
    __nv_bfloat16 *Sh, *Sl, *X2h, *X2l, *Hh, *Hl, *Wth, *Wtl;
};

static void get_scratch(Scratch& s) {
    cudaGetSymbolAddress((void**)&s.S,  g_S);
    cudaGetSymbolAddress((void**)&s.V,  g_V);
    cudaGetSymbolAddress((void**)&s.X1, g_X1);
    cudaGetSymbolAddress((void**)&s.X2, g_X2);
    cudaGetSymbolAddress((void**)&s.Lh, g_Lh);   cudaGetSymbolAddress((void**)&s.Ll, g_Ll);
    cudaGetSymbolAddress((void**)&s.Rh, g_Rh);   cudaGetSymbolAddress((void**)&s.Rl, g_Rl);
    cudaGetSymbolAddress((void**)&s.Qh, g_Qh);   cudaGetSymbolAddress((void**)&s.Ql, g_Ql);
    cudaGetSymbolAddress((void**)&s.Kh, g_Kh);   cudaGetSymbolAddress((void**)&s.Kl, g_Kl);
    cudaGetSymbolAddress((void**)&s.Vth, g_Vth); cudaGetSymbolAddress((void**)&s.Vtl, g_Vtl);
    cudaGetSymbolAddress((void**)&s.Sh, g_Sh);   cudaGetSymbolAddress((void**)&s.Sl, g_Sl);
    cudaGetSymbolAddress((void**)&s.X2h, g_X2h); cudaGetSymbolAddress((void**)&s.X2l, g_X2l);
    cudaGetSymbolAddress((void**)&s.Hh, g_Hh);   cudaGetSymbolAddress((void**)&s.Hl, g_Hl);
    cudaGetSymbolAddress((void**)&s.Wth, g_Wth); cudaGetSymbolAddress((void**)&s.Wtl, g_Wtl);
}

static void set_attrs() {
    cudaFuncSetAttribute((const void*)hmma_gemm<EPI_NONE,  true >, cudaFuncAttributeMaxDynamicSharedMemorySize, SMEM_TOTAL_GEMM);
    cudaFuncSetAttribute((const void*)hmma_gemm<EPI_NONE,  false>, cudaFuncAttributeMaxDynamicSharedMemorySize, SMEM_TOTAL_GEMM);
    cudaFuncSetAttribute((const void*)hmma_gemm<EPI_GAUSS, false>, cudaFuncAttributeMaxDynamicSharedMemorySize, SMEM_TOTAL_GEMM);
    cudaFuncSetAttribute((const void*)hmma_gemm<EPI_BIAS,  false>, cudaFuncAttributeMaxDynamicSharedMemorySize, SMEM_TOTAL_GEMM);
    cudaFuncSetAttribute((const void*)hmma_gemm<EPI_RELU,  true >, cudaFuncAttributeMaxDynamicSharedMemorySize, SMEM_TOTAL_GEMM);
    cudaFuncSetAttribute((const void*)hmma_gemm<EPI_RESID, false>, cudaFuncAttributeMaxDynamicSharedMemorySize, SMEM_TOTAL_GEMM);
}

static void run_branch(const Scratch& s,
                       const __nv_bfloat16* Qh_src, const __nv_bfloat16* Ql_src,
                       const __nv_bfloat16* KVh_src, const __nv_bfloat16* KVl_src,
                       const float* KV_f32, const float* biasMat, int gauss,
                       const float* WQ, const float* WK, const float* WV,
                       const float* ln1g, const float* ln1b,
                       const float* w1, const float* b1,
                       const float* w2, const float* b2,
                       const float* ln2g, const float* ln2b,
                       float* outp)
{
    const dim3 tW(16, 16), tB(32, 8);
    const int WSZ = D_DIM * D_DIM;
    const float scale = 0.04419417382415922f;  // 1/sqrt(512)

    // transpose+split the five weight matrices
    tconv_kernel<<<tW, tB>>>(WQ, s.Wth + 0 * WSZ, s.Wtl + 0 * WSZ, D_DIM, D_DIM);
    tconv_kernel<<<tW, tB>>>(WK, s.Wth + 1 * WSZ, s.Wtl + 1 * WSZ, D_DIM, D_DIM);
    tconv_kernel<<<tW, tB>>>(WV, s.Wth + 2 * WSZ, s.Wtl + 2 * WSZ, D_DIM, D_DIM);
    tconv_kernel<<<tW, tB>>>(w1, s.Wth + 3 * WSZ, s.Wtl + 3 * WSZ, D_DIM, D_DIM);
    tconv_kernel<<<tW, tB>>>(w2, s.Wth + 4 * WSZ, s.Wtl + 4 * WSZ, D_DIM, D_DIM);

    const dim3 gP(D_DIM / 128, N_TOK / 128);   // (4, 32)
    const dim3 gS(N_TOK / 128, N_TOK / 128);   // (32, 32)

    // projections
    hmma_gemm<EPI_NONE, true><<<gP, 256, SMEM_TOTAL_GEMM>>>(
        Qh_src, Ql_src, s.Wth + 0 * WSZ, s.Wtl + 0 * WSZ,
        nullptr, s.Qh, s.Ql, D_DIM, D_DIM, nullptr, nullptr, 0.f);
    hmma_gemm<EPI_NONE, true><<<gP, 256, SMEM_TOTAL_GEMM>>>(
        KVh_src, KVl_src, s.Wth + 1 * WSZ, s.Wtl + 1 * WSZ,
        nullptr, s.Kh, s.Kl, D_DIM, D_DIM, nullptr, nullptr, 0.f);
    hmma_gemm<EPI_NONE, false><<<gP, 256, SMEM_TOTAL_GEMM>>>(
        KVh_src, KVl_src, s.Wth + 2 * WSZ, s.Wtl + 2 * WSZ,
        s.V, nullptr, nullptr, D_DIM, D_DIM, nullptr, nullptr, 0.f);
    tconv_kernel<<<dim3(16, 128), tB>>>(s.V, s.Vth, s.Vtl, N_TOK, D_DIM);

    // scores + fused softmax/split
    if (gauss)
        hmma_gemm<EPI_GAUSS, false><<<gS, 256, SMEM_TOTAL_GEMM>>>(
            s.Qh, s.Ql, s.Kh, s.Kl, s.S, nullptr, nullptr, D_DIM, N_TOK, biasMat, nullptr, scale);
    else
        hmma_gemm<EPI_BIAS, false><<<gS, 256, SMEM_TOTAL_GEMM>>>(
            s.Qh, s.Ql, s.Kh, s.Kl, s.S, nullptr, nullptr, D_DIM, N_TOK, biasMat, nullptr, scale);
    softmax_split_kernel<<<N_TOK, 256>>>(s.S, s.Sh, s.Sl);

    // att @ V
    hmma_gemm<EPI_NONE, false><<<gP, 256, SMEM_TOTAL_GEMM>>>(
        s.Sh, s.Sl, s.Vth, s.Vtl, s.X1, nullptr, nullptr, N_TOK, D_DIM, nullptr, nullptr, 0.f);
    layernorm_kernel<<<N_TOK, 128>>>(s.X1, KV_f32, ln1g, ln1b, s.X2, s.X2h, s.X2l);

    // FFN
    hmma_gemm<EPI_RELU, true><<<gP, 256, SMEM_TOTAL_GEMM>>>(
        s.X2h, s.X2l, s.Wth + 3 * WSZ, s.Wtl + 3 * WSZ,
        nullptr, s.Hh, s.Hl, D_DIM, D_DIM, b1, nullptr, 0.f);
    hmma_gemm<EPI_RESID, false><<<gP, 256, SMEM_TOTAL_GEMM>>>(
        s.Hh, s.Hl, s.Wth + 4 * WSZ, s.Wtl + 4 * WSZ,
        s.X1, nullptr, nullptr, D_DIM, D_DIM, b2, s.X2, 0.f);
    layernorm_kernel<<<N_TOK, 128>>>(s.X1, nullptr, ln2g, ln2b, outp, nullptr, nullptr);
}

extern "C" void kernel_launch(void* const* d_in, const int* in_sizes, int n_in,
                              void* d_out, int out_size)
{
    (void)in_sizes; (void)n_in; (void)out_size;
    Scratch s;
    get_scratch(s);
    set_attrs();

    const float* R  = (const float*)d_in[0];
    const float* L  = (const float*)d_in[1];
    const float* Dg = (const float*)d_in[2];
    const float* De = (const float*)d_in[3];

    const float* WQ_r = (const float*)d_in[4];
    const float* WK_r = (const float*)d_in[5];
    const float* WV_r = (const float*)d_in[6];
    const float* ln_r1_g = (const float*)d_in[7];
    const float* ln_r1_b = (const float*)d_in[8];
    const float* ffn_r_w1 = (const float*)d_in[9];
    const float* ffn_r_b1 = (const float*)d_in[10];
    const float* ffn_r_w2 = (const float*)d_in[11];
    const float* ffn_r_b2 = (const float*)d_in[12];
    const float* ln_r2_g = (const float*)d_in[13];
    const float* ln_r2_b = (const float*)d_in[14];

    const float* WQ_l = (const float*)d_in[15];
    const float* WK_l = (const float*)d_in[16];
    const float* WV_l = (const float*)d_in[17];
    const float* ln_l1_g = (const float*)d_in[18];
    const float* ln_l1_b = (const float*)d_in[19];
    const float* ffn_l_w1 = (const float*)d_in[20];
    const float* ffn_l_b1 = (const float*)d_in[21];
    const float* ffn_l_w2 = (const float*)d_in[22];
    const float* ffn_l_b2 = (const float*)d_in[23];
    const float* ln_l2_g = (const float*)d_in[24];
    const float* ln_l2_b = (const float*)d_in[25];

    float* out = (float*)d_out;

    // split the two token matrices once
    const int n4 = N_TOK * D_DIM / 4;
    split_kernel<<<n4 / 256, 256>>>(L, s.Lh, s.Ll, n4);
    split_kernel<<<n4 / 256, 256>>>(R, s.Rh, s.Rl, n4);

    // R branch: Q from L, K/V from R, resid R, Gaussian bias from De
    run_branch(s, s.Lh, s.Ll, s.Rh, s.Rl, R, De, 1,
               WQ_r, WK_r, WV_r, ln_r1_g, ln_r1_b,
               ffn_r_w1, ffn_r_b1, ffn_r_w2, ffn_r_b2, ln_r2_g, ln_r2_b,
               out);

    // L branch: Q from R, K/V from L, resid L, bias Dg (direct add)
    run_branch(s, s.Rh, s.Rl, s.Lh, s.Ll, L, Dg, 0,
               WQ_l, WK_l, WV_l, ln_l1_g, ln_l1_b,
               ffn_l_w1, ffn_l_b1, ffn_l_w2, ffn_l_b2, ln_l2_g, ln_l2_b,
               out + (size_t)N_TOK * D_DIM);
}